// round 6
// baseline (speedup 1.0000x reference)
#include <cuda_runtime.h>
#include <cuda_fp16.h>
#include <math.h>
#include <stdint.h>

#define N_NODES 50000
#define N_EDGES 800000
#define HID     384
#define DOUT    128
#define TM      64                  // edges per tile
#define NTILES  (N_EDGES / TM)      // 12500

// ---------------- device scratch ----------------
__device__ __half g_P16[(size_t)N_NODES * HID];   // vc @ W1[0:128]        (fp16)
__device__ __half g_Q16[(size_t)N_NODES * HID];   // vc @ W1[128:256] + b1 (fp16)
__device__ float  g_W23[HID * DOUT];              // W2[:,1:] @ W3
__device__ float  g_w20[HID];                     // W2[:,0]
__device__ float  g_c0[DOUT];                     // b2[1:] @ W3
__device__ float  g_b20;                          // b2[0]

// ---------------- helpers ----------------
__device__ __forceinline__ uint32_t f2tf(float f) {
    uint32_t u; asm("cvt.rna.tf32.f32 %0, %1;" : "=r"(u) : "f"(f)); return u;
}
__device__ __forceinline__ void mma_tf32(float c[4],
        uint32_t a0, uint32_t a1, uint32_t a2, uint32_t a3,
        uint32_t b0, uint32_t b1) {
    asm volatile("mma.sync.aligned.m16n8k8.row.col.f32.tf32.tf32.f32 "
        "{%0,%1,%2,%3}, {%4,%5,%6,%7}, {%8,%9}, {%0,%1,%2,%3};"
        : "+f"(c[0]), "+f"(c[1]), "+f"(c[2]), "+f"(c[3])
        : "r"(a0), "r"(a1), "r"(a2), "r"(a3), "r"(b0), "r"(b1));
}
__device__ __forceinline__ void mma_f16(float c[4],
        uint32_t a0, uint32_t a1, uint32_t a2, uint32_t a3,
        uint32_t b0, uint32_t b1) {
    asm volatile("mma.sync.aligned.m16n8k16.row.col.f32.f16.f16.f32 "
        "{%0,%1,%2,%3}, {%4,%5,%6,%7}, {%8,%9}, {%0,%1,%2,%3};"
        : "+f"(c[0]), "+f"(c[1]), "+f"(c[2]), "+f"(c[3])
        : "r"(a0), "r"(a1), "r"(a2), "r"(a3), "r"(b0), "r"(b1));
}
__device__ __forceinline__ uint32_t f22h2u(float a, float b) {
    __half2 h = __floats2half2_rn(a, b);
    return *reinterpret_cast<uint32_t*>(&h);
}
__device__ __forceinline__ float2 u2f2(uint32_t u) {
    __half2 h = *reinterpret_cast<__half2*>(&u);
    return __half22float2(h);
}
#define GROUP_BAR(wm) asm volatile("bar.sync %0, 128;" :: "r"((wm) + 1) : "memory")

// ---------------- tiny precompute kernels ----------------
__global__ void k_w23(const float* __restrict__ W2, const float* __restrict__ W3) {
    __shared__ float s[512];
    int k = blockIdx.x;          // 0..383
    int t = threadIdx.x;         // 0..127
    for (int j = t; j < 512; j += 128) s[j] = W2[k * 513 + 1 + j];
    __syncthreads();
    float acc = 0.f;
#pragma unroll 8
    for (int j = 0; j < 512; j++) acc = fmaf(s[j], W3[j * DOUT + t], acc);
    g_W23[k * DOUT + t] = acc;
}

__global__ void k_misc(const float* __restrict__ W2, const float* __restrict__ b2,
                       const float* __restrict__ W3) {
    int t = threadIdx.x;  // 512 threads
    if (t < HID) g_w20[t] = W2[t * 513];
    if (t < DOUT) {
        float acc = 0.f;
        for (int j = 0; j < 512; j++) acc = fmaf(b2[1 + j], W3[j * DOUT + t], acc);
        g_c0[t] = acc;
    }
    if (t == 0) g_b20 = b2[0];
}

// ---------------- k_pq: P|Q node GEMM (tf32 mma), fp16 output ----------------
#define PQ_TM 32
__global__ void __launch_bounds__(256) k_pq(const float* __restrict__ vc,
                                            const float* __restrict__ W1,
                                            const float* __restrict__ b1) {
    extern __shared__ uint32_t smu[];
    uint32_t* s_w = smu;               // [128][136]
    uint32_t* s_x = smu + 128 * 136;   // [32][132]
    int t = threadIdx.x;
    int chunk = blockIdx.x;
    int half = chunk / 3, nc = chunk - half * 3;
    int n0t = blockIdx.y * PQ_TM;

    for (int i = t; i < 128 * 128; i += 256) {
        int k = i >> 7, n = i & 127;
        s_w[k * 136 + n] = f2tf(W1[(size_t)(half * 128 + k) * HID + nc * 128 + n]);
    }
    for (int i = t; i < PQ_TM * 128; i += 256) {
        int r = i >> 7, k = i & 127;
        int node = n0t + r; if (node >= N_NODES) node = N_NODES - 1;
        s_x[r * 132 + k] = f2tf(vc[(size_t)node * 128 + k]);
    }
    __syncthreads();

    int warp = t >> 5, lane = t & 31;
    int wm = warp >> 2, wn = warp & 3;
    int g = lane >> 2, tt = lane & 3;
    int mb = wm * 16;

    float acc[4][4];
#pragma unroll
    for (int j = 0; j < 4; j++) {
        int col = nc * 128 + wn * 32 + j * 8 + 2 * tt;
        float bv0 = half ? b1[col] : 0.f;
        float bv1 = half ? b1[col + 1] : 0.f;
        acc[j][0] = bv0; acc[j][1] = bv1; acc[j][2] = bv0; acc[j][3] = bv1;
    }
#pragma unroll 4
    for (int ks = 0; ks < 16; ks++) {
        int k0 = ks * 8;
        uint32_t a0 = s_x[(mb + g) * 132 + k0 + tt];
        uint32_t a1 = s_x[(mb + g + 8) * 132 + k0 + tt];
        uint32_t a2 = s_x[(mb + g) * 132 + k0 + tt + 4];
        uint32_t a3 = s_x[(mb + g + 8) * 132 + k0 + tt + 4];
#pragma unroll
        for (int j = 0; j < 4; j++) {
            int n0 = wn * 32 + j * 8;
            uint32_t b0 = s_w[(k0 + tt) * 136 + n0 + g];
            uint32_t b1r = s_w[(k0 + tt + 4) * 136 + n0 + g];
            mma_tf32(acc[j], a0, a1, a2, a3, b0, b1r);
        }
    }
    __half* dstp = half ? g_Q16 : g_P16;
    int r_lo = n0t + mb + g, r_hi = r_lo + 8;
#pragma unroll
    for (int j = 0; j < 4; j++) {
        int col = nc * 128 + wn * 32 + j * 8 + 2 * tt;
        if (r_lo < N_NODES)
            *(uint32_t*)&dstp[(size_t)r_lo * HID + col] = f22h2u(acc[j][0], acc[j][1]);
        if (r_hi < N_NODES)
            *(uint32_t*)&dstp[(size_t)r_hi * HID + col] = f22h2u(acc[j][2], acc[j][3]);
    }
}

// ---------------- k_fused: 512 threads, 16 warps (4m x 4n) ----------------
__global__ void __launch_bounds__(512, 1) k_fused(
    const float* __restrict__ ve1, const float* __restrict__ ve2,
    const int*   __restrict__ src, const int* __restrict__ dst,
    const float* __restrict__ W1,  const float* __restrict__ b3,
    float* __restrict__ out)
{
    extern __shared__ uint32_t sm[];
    uint32_t* s_wve = sm;                       // 384*64 words
    uint32_t* s_w23 = s_wve + 384 * 64;         // 128*192 words
    uint32_t* s_x   = s_w23 + 128 * 192;        // 64*64
    uint32_t* s_h   = s_x + 64 * 64;            // 64*64
    float*    s_w20 = (float*)(s_h + 64 * 64);  // 384
    float*    s_gate = s_w20 + HID;             // 64
    int*      s_src  = (int*)(s_gate + 64);     // 64
    int*      s_dst  = s_src + 64;              // 64

    int t = threadIdx.x;
    int warp = t >> 5, lane = t & 31;
    int wm = warp >> 2, wn = warp & 3;          // 4 x 4 warp grid
    int g = lane >> 2, tt = lane & 3;
    uint32_t gsw = (uint32_t)g << 2;
    int rl = wm * 16 + g, rh = rl + 8;          // this warp's row pair

    // ---- load weights into smem (once) ----
    for (int i = t; i < 384 * 64; i += 512) {       // Wve[n][k] = W1[256+k][n]
        int n = i >> 6, w = i & 63;
        int k = 2 * w;
        s_wve[(n << 6) + (w ^ ((n & 7) << 2))] =
            f22h2u(W1[(size_t)(256 + k) * HID + n], W1[(size_t)(256 + k + 1) * HID + n]);
    }
    for (int i = t; i < 128 * 192; i += 512) {      // W23s[n][k] = g_W23[k][n]
        int n = i / 192, w = i - n * 192;
        int k = 2 * w;
        s_w23[n * 192 + (w ^ ((n & 7) << 2))] =
            f22h2u(g_W23[k * DOUT + n], g_W23[(k + 1) * DOUT + n]);
    }
    if (t < HID) s_w20[t] = g_w20[t];

    // per-thread epilogue constants
    float2 c0r[4], b3r[4];
#pragma unroll
    for (int j = 0; j < 4; j++) {
        int col = wn * 32 + j * 8 + 2 * tt;
        c0r[j] = *(const float2*)&g_c0[col];
        b3r[j] = *(const float2*)&b3[col];
    }
    float b20 = g_b20;
    // gate ownership: each warp reduces 4 rows within its wm group
    int grow = wm * 16 + wn * 4 + (lane >> 3);
    int gsub = lane & 7;

    for (int tile = blockIdx.x; tile < NTILES; tile += gridDim.x) {
        int e0 = tile * TM;
        __syncthreads();    // all prior readers of s_x/s_gate done
        // ---- stage edge features + indices ----
        if (t < 64) s_src[t] = src[e0 + t];
        else if (t < 128) s_dst[t - 64] = dst[e0 + t - 64];
        for (int i = t; i < 64 * 64; i += 512) {
            int r = i >> 6, w = i & 63;
            float2 v;
            if (w < 32) v = *(const float2*)&ve1[(size_t)(e0 + r) * 64 + 2 * w];
            else        v = *(const float2*)&ve2[(size_t)(e0 + r) * 64 + 2 * w - 64];
            s_x[(r << 6) + (w ^ ((r & 7) << 2))] = f22h2u(v.x, v.y);
        }
        __syncthreads();

        float acc2[4][4];
#pragma unroll
        for (int j = 0; j < 4; j++)
#pragma unroll
            for (int i = 0; i < 4; i++) acc2[j][i] = 0.f;
        float gacc = 0.f;

        // prefetch P/Q fragments for chunk 0
        uint32_t pq[2][4][2];
        {
            const __half* Pl = g_P16 + (size_t)s_src[rl] * HID;
            const __half* Ql = g_Q16 + (size_t)s_dst[rl] * HID;
            const __half* Ph = g_P16 + (size_t)s_src[rh] * HID;
            const __half* Qh = g_Q16 + (size_t)s_dst[rh] * HID;
#pragma unroll
            for (int j = 0; j < 4; j++) {
                int cc = wn * 32 + j * 8 + 2 * tt;
                pq[0][j][0] = *(const uint32_t*)(Pl + cc);
                pq[0][j][1] = *(const uint32_t*)(Ql + cc);
                pq[1][j][0] = *(const uint32_t*)(Ph + cc);
                pq[1][j][1] = *(const uint32_t*)(Qh + cc);
            }
        }

#pragma unroll 1
        for (int c = 0; c < 3; c++) {
            // ---- GEMM1 chunk: x @ Wve (this warp: rows rl/rh, cols wn*32..) ----
            float acc1[4][4];
#pragma unroll
            for (int j = 0; j < 4; j++)
#pragma unroll
                for (int i = 0; i < 4; i++) acc1[j][i] = 0.f;
#pragma unroll
            for (int ks = 0; ks < 8; ks++) {
                int wa = 8 * ks + tt, wb = wa + 4;
                uint32_t a0 = s_x[(rl << 6) + (wa ^ gsw)];
                uint32_t a1 = s_x[(rh << 6) + (wa ^ gsw)];
                uint32_t a2 = s_x[(rl << 6) + (wb ^ gsw)];
                uint32_t a3 = s_x[(rh << 6) + (wb ^ gsw)];
#pragma unroll
                for (int j = 0; j < 4; j++) {
                    int n = 128 * c + wn * 32 + j * 8 + g;
                    uint32_t b0 = s_wve[(n << 6) + (wa ^ gsw)];
                    uint32_t b1 = s_wve[(n << 6) + (wb ^ gsw)];
                    mma_f16(acc1[j], a0, a1, a2, a3, b0, b1);
                }
            }
            // ---- epilogue: + P + Q, relu, store h chunk ----
#pragma unroll
            for (int j = 0; j < 4; j++) {
                int wcl = wn * 16 + j * 4 + tt;
                float2 pl = u2f2(pq[0][j][0]), ql = u2f2(pq[0][j][1]);
                float2 ph = u2f2(pq[1][j][0]), qh = u2f2(pq[1][j][1]);
                float h0 = fmaxf(acc1[j][0] + pl.x + ql.x, 0.f);
                float h1 = fmaxf(acc1[j][1] + pl.y + ql.y, 0.f);
                float h2 = fmaxf(acc1[j][2] + ph.x + qh.x, 0.f);
                float h3 = fmaxf(acc1[j][3] + ph.y + qh.y, 0.f);
                s_h[(rl << 6) + (wcl ^ gsw)] = f22h2u(h0, h1);
                s_h[(rh << 6) + (wcl ^ gsw)] = f22h2u(h2, h3);
            }
            // ---- prefetch P/Q for next chunk (latency hidden by gate+GEMM2) ----
            if (c < 2) {
                const __half* Pl = g_P16 + (size_t)s_src[rl] * HID + 128 * (c + 1);
                const __half* Ql = g_Q16 + (size_t)s_dst[rl] * HID + 128 * (c + 1);
                const __half* Ph = g_P16 + (size_t)s_src[rh] * HID + 128 * (c + 1);
                const __half* Qh = g_Q16 + (size_t)s_dst[rh] * HID + 128 * (c + 1);
#pragma unroll
                for (int j = 0; j < 4; j++) {
                    int cc = wn * 32 + j * 8 + 2 * tt;
                    pq[0][j][0] = *(const uint32_t*)(Pl + cc);
                    pq[0][j][1] = *(const uint32_t*)(Ql + cc);
                    pq[1][j][0] = *(const uint32_t*)(Ph + cc);
                    pq[1][j][1] = *(const uint32_t*)(Qh + cc);
                }
            }
            GROUP_BAR(wm);     // h chunk visible within wm group

            // ---- gate partial: 4 rows per warp, 8 lanes per row ----
#pragma unroll
            for (int i = 0; i < 8; i++) {
                int w = gsub + 8 * i;
                float2 hv = u2f2(s_h[(grow << 6) + (w ^ ((grow & 7) << 2))]);
                float2 wv = *(const float2*)&s_w20[128 * c + 2 * w];
                gacc = fmaf(hv.x, wv.x, fmaf(hv.y, wv.y, gacc));
            }
            // ---- GEMM2 partial: acc2 += h_chunk @ W23[kchunk] ----
#pragma unroll
            for (int ks = 0; ks < 8; ks++) {
                int wa = 8 * ks + tt, wb = wa + 4;
                uint32_t a0 = s_h[(rl << 6) + (wa ^ gsw)];
                uint32_t a1 = s_h[(rh << 6) + (wa ^ gsw)];
                uint32_t a2 = s_h[(rl << 6) + (wb ^ gsw)];
                uint32_t a3 = s_h[(rh << 6) + (wb ^ gsw)];
#pragma unroll
                for (int j = 0; j < 4; j++) {
                    int n = wn * 32 + j * 8 + g;
                    int w0 = 64 * c + 8 * ks + tt;
                    uint32_t b0 = s_w23[n * 192 + (w0 ^ gsw)];
                    uint32_t b1 = s_w23[n * 192 + ((w0 + 4) ^ gsw)];
                    mma_f16(acc2[j], a0, a1, a2, a3, b0, b1);
                }
            }
            GROUP_BAR(wm);     // group's GEMM2/gate reads done before next h write
        }
        // ---- gate finalize: reduce across 8 lanes of each row ----
        gacc += __shfl_xor_sync(0xffffffffu, gacc, 1);
        gacc += __shfl_xor_sync(0xffffffffu, gacc, 2);
        gacc += __shfl_xor_sync(0xffffffffu, gacc, 4);
        if (gsub == 0) s_gate[grow] = 1.f / (1.f + expf(-(gacc + b20)));
        GROUP_BAR(wm);         // gate rows of this wm group visible
        // ---- output epilogue ----
        float kl = s_gate[rl], kh = s_gate[rh];
#pragma unroll
        for (int j = 0; j < 4; j++) {
            int col = wn * 32 + j * 8 + 2 * tt;
            float2 o0, o1;
            o0.x = fmaf(kl, acc2[j][0] + c0r[j].x, b3r[j].x);
            o0.y = fmaf(kl, acc2[j][1] + c0r[j].y, b3r[j].y);
            o1.x = fmaf(kh, acc2[j][2] + c0r[j].x, b3r[j].x);
            o1.y = fmaf(kh, acc2[j][3] + c0r[j].y, b3r[j].y);
            *(float2*)&out[(size_t)(e0 + rl) * DOUT + col] = o0;
            *(float2*)&out[(size_t)(e0 + rh) * DOUT + col] = o1;
        }
    }
}

// ---------------- launch ----------------
extern "C" void kernel_launch(void* const* d_in, const int* in_sizes, int n_in,
                              void* d_out, int out_size) {
    const float* vc  = (const float*)d_in[0];
    const float* ve1 = (const float*)d_in[1];
    const float* ve2 = (const float*)d_in[2];
    const int*   src = (const int*)  d_in[3];
    const int*   dst = (const int*)  d_in[4];
    const float* W1  = (const float*)d_in[5];
    const float* b1  = (const float*)d_in[6];
    const float* W2  = (const float*)d_in[7];
    const float* b2  = (const float*)d_in[8];
    const float* W3  = (const float*)d_in[9];
    const float* b3  = (const float*)d_in[10];
    float* out = (float*)d_out;

    const int smem_pq = (128 * 136 + 32 * 132) * 4;                        // 86528
    const int smem_f  = (384 * 64 + 128 * 192 + 64 * 64 + 64 * 64) * 4
                        + (HID + 64) * 4 + 64 * 4 + 64 * 4;                // 231680

    cudaFuncSetAttribute(k_pq,    cudaFuncAttributeMaxDynamicSharedMemorySize, smem_pq);
    cudaFuncSetAttribute(k_fused, cudaFuncAttributeMaxDynamicSharedMemorySize, smem_f);

    k_w23 <<<HID, 128>>>(W2, W3);
    k_misc<<<1, 512>>>(W2, b2, W3);
    k_pq  <<<dim3(6, (N_NODES + PQ_TM - 1) / PQ_TM), 256, smem_pq>>>(vc, W1, b1);
    k_fused<<<148, 512, smem_f>>>(ve1, ve2, src, dst, W1, b3, out);
}